// round 16
// baseline (speedup 1.0000x reference)
#include <cuda_runtime.h>

// ManifoldValuedVolterra on S^2 — 4-output-channels-per-thread round.
//
// LOCKED per-pair numerics (score-critical, bitwise identical to R15):
//   dot = rn((t0 + t2) + t1)  [SIMD fold], clip +/-(1 - 1e-6),
//   s2 = fma(-d,d,1), g = acosf(d)*rsqrtf(s2), r = fma(-d,p,q),
//   lg = g*r, einsum acc = fma(w, lg, acc) i-ascending, taps in order.
// Change vs R15: one thread computes ALL 4 output channels, so the 3 q
// loads + addressing per (tap,i) are amortized x4 (55 -> ~41 slots/pair)
// and the 4 independent chains give ILP to hide acosf latency.

#define NC   4
#define ND   64
#define NH   64
#define NW_  64
#define NDO  62
#define NTAP 27

__global__ __launch_bounds__(128)
void mvv_kernel(const float* __restrict__ x,
                const float* __restrict__ w1,
                const float* __restrict__ w2,
                const float* __restrict__ w3,
                float* __restrict__ out)
{
    // Packed weights: sw[(o*27+tap)*4 + i] = (w1, w2, w3, 0)
    __shared__ float4 sw[NC * NTAP * NC];

    const int t = threadIdx.y * 32 + threadIdx.x;
    for (int j = t; j < NC * NTAP * NC; j += 128) {
        sw[j] = make_float4(w1[j], w2[j], w3[j], 0.0f);
    }
    __syncthreads();

    const int ox = blockIdx.x * 32 + threadIdx.x;
    const int oy = blockIdx.y * 4 + threadIdx.y;
    const int bz = blockIdx.z;            // 0..123 = b*NDO + oz
    const int b  = bz / NDO;
    const int oz = bz - b * NDO;
    if (ox >= NDO || oy >= NDO) return;

    const int plane = ND * NH * NW_ * 3;              // channel stride (floats)
    const float* xb = x + (long)b * NC * plane;       // batch base

    // Center points p for all 4 output channels
    const int pOff = (((oz + 1) * NH + (oy + 1)) * NW_ + (ox + 1)) * 3;
    float px[NC], py[NC], pz[NC];
#pragma unroll
    for (int o = 0; o < NC; o++) {
        const float* pp = xb + o * plane + pOff;
        px[o] = __ldg(pp + 0);
        py[o] = __ldg(pp + 1);
        pz[o] = __ldg(pp + 2);
    }

    // Accumulators: S[o][m*3 + comp]
    float S[NC][9];
#pragma unroll
    for (int o = 0; o < NC; o++)
#pragma unroll
        for (int j = 0; j < 9; j++) S[o][j] = 0.0f;

    const float CLIP_LO = (float)(-1.0 + 1e-6);
    const float CLIP_HI = (float)( 1.0 - 1e-6);

    const int vox0 = ((oz * NH + oy) * NW_ + ox) * 3;   // tap (0,0,0) corner

#pragma unroll 1
    for (int kz = 0; kz < 3; kz++) {
#pragma unroll 1
        for (int ky = 0; ky < 3; ky++) {
            const int rowOff = vox0 + ((kz * NH + ky) * NW_) * 3;
            const int tapRow = (kz * 3 + ky) * 3;
#pragma unroll
            for (int kx = 0; kx < 3; kx++) {
                const int tap  = tapRow + kx;
                const int qOff = rowOff + kx * 3;

#pragma unroll
                for (int i = 0; i < NC; i++) {
                    const float* q = xb + qOff + i * plane;
                    const float qx = __ldg(q + 0);
                    const float qy = __ldg(q + 1);
                    const float qz = __ldg(q + 2);

#pragma unroll
                    for (int o = 0; o < NC; o++) {
                        // dot SIMD-FOLD (LOCKED): (t0 + t2) + t1, rn
                        float d = __fadd_rn(__fadd_rn(__fmul_rn(px[o], qx),
                                                      __fmul_rn(pz[o], qz)),
                                            __fmul_rn(py[o], qy));
                        d = fminf(fmaxf(d, CLIP_LO), CLIP_HI);

                        // g = acos(d)/sin(acos(d))
                        const float s2 = fmaf(-d, d, 1.0f);
                        const float g  = acosf(d) * rsqrtf(s2);

                        // lg = g * (q - d*p)
                        const float lx = g * fmaf(-d, px[o], qx);
                        const float ly = g * fmaf(-d, py[o], qy);
                        const float lz = g * fmaf(-d, pz[o], qz);

                        const float4 wv = sw[(o * NTAP + tap) * 4 + i];

                        S[o][0] = fmaf(wv.x, lx, S[o][0]);
                        S[o][1] = fmaf(wv.x, ly, S[o][1]);
                        S[o][2] = fmaf(wv.x, lz, S[o][2]);
                        S[o][3] = fmaf(wv.y, lx, S[o][3]);
                        S[o][4] = fmaf(wv.y, ly, S[o][4]);
                        S[o][5] = fmaf(wv.y, lz, S[o][5]);
                        S[o][6] = fmaf(wv.z, lx, S[o][6]);
                        S[o][7] = fmaf(wv.z, ly, S[o][7]);
                        S[o][8] = fmaf(wv.z, lz, S[o][8]);
                    }
                }
            }
        }
    }

    // Epilogue per output channel
#pragma unroll
    for (int o = 0; o < NC; o++) {
        const float vx = fmaf(S[o][3], S[o][6], S[o][0]);
        const float vy = fmaf(S[o][4], S[o][7], S[o][1]);
        const float vz = fmaf(S[o][5], S[o][8], S[o][2]);

        const float n2 = __fadd_rn(fmaf(vz, vz, fmaf(vy, vy,
                                        __fmul_rn(vx, vx))), 1e-12f);
        const float n  = sqrtf(n2);
        float sn, cn;
        sincosf(n, &sn, &cn);
        const float k = __fdiv_rn(sn, n);

        float* op = out + (((((long)b * NC + o) * NDO + oz) * NDO + oy) * NDO + ox) * 3;
        op[0] = fmaf(cn, px[o], __fmul_rn(k, vx));
        op[1] = fmaf(cn, py[o], __fmul_rn(k, vy));
        op[2] = fmaf(cn, pz[o], __fmul_rn(k, vz));
    }
}

extern "C" void kernel_launch(void* const* d_in, const int* in_sizes, int n_in,
                              void* d_out, int out_size)
{
    const float* x  = (const float*)d_in[0];
    const float* w1 = (const float*)d_in[1];
    const float* w2 = (const float*)d_in[2];
    const float* w3 = (const float*)d_in[3];
    float* out = (float*)d_out;

    dim3 blk(32, 4, 1);
    dim3 grd((NDO + 31) / 32, (NDO + 3) / 4, 2 * NDO);  // (2, 16, 124)
    mvv_kernel<<<grd, blk>>>(x, w1, w2, w3, out);
}

// round 17
// speedup vs baseline: 1.1377x; 1.1377x over previous
#include <cuda_runtime.h>

// ManifoldValuedVolterra on S^2 — custom-polynomial acos round (R15 base).
//
// LOCKED numerics: dot = rn((t0 + t2) + t1) [SIMD fold matching the
// reference's vectorized reduce], clip +/-(1 - 1e-6). Only delta-d is
// pole-amplified; g-implementation error is unamplified (R2/R9 nulls), so
// we replace libm acosf (~19 slots, IEEE) with:
//   acos(|d|) = sqrt(1-|d|) * P7(|d|)   (minimax, |err| <= 2e-8)
//   sqrt(1-|d|) = (1-|d|) * MUFU.RSQ    (clip guarantees arg >= 1e-6)
//   acos(d) = d < 0 ? pi - acos(|d|) : acos(|d|)
//   g = acos(d) * rsqrtf(fma(-d,d,1))
// ~13 slots; per-term rel error ~3e-7 -> adds ~2e-5 in quadrature.

#define NC   4
#define ND   64
#define NH   64
#define NW_  64
#define NDO  62
#define NTAP 27

__device__ __forceinline__ float acos_fast(float d) {
    const float a  = fabsf(d);
    const float om = 1.0f - a;            // >= 1e-6 after clip
    const float sq = om * rsqrtf(om);     // sqrt(1-a), ~2 ulp
    float p = fmaf(-0.0012624911f, a, 0.0066700901f);
    p = fmaf(p, a, -0.0170881256f);
    p = fmaf(p, a,  0.0308918810f);
    p = fmaf(p, a, -0.0501743046f);
    p = fmaf(p, a,  0.0889789874f);
    p = fmaf(p, a, -0.2145988016f);
    p = fmaf(p, a,  1.5707963050f);
    const float t = sq * p;               // acos(|d|)
    return (d < 0.0f) ? (3.14159265358979f - t) : t;
}

__global__ __launch_bounds__(128)
void mvv_kernel(const float* __restrict__ x,
                const float* __restrict__ w1,
                const float* __restrict__ w2,
                const float* __restrict__ w3,
                float* __restrict__ out)
{
    // Packed weights: sw[(o*27+tap)*4 + i] = (w1, w2, w3, 0)
    __shared__ float4 sw[NC * NTAP * NC];

    const int t = threadIdx.y * 32 + threadIdx.x;
    for (int j = t; j < NC * NTAP * NC; j += 128) {
        sw[j] = make_float4(w1[j], w2[j], w3[j], 0.0f);
    }
    __syncthreads();

    const int ox = blockIdx.x * 32 + threadIdx.x;
    const int oy = blockIdx.y * 4 + threadIdx.y;
    // blockIdx.z encodes (b, oz, o): z = (b*NDO + oz)*NC + o
    const int z  = blockIdx.z;
    const int o  = z & 3;
    const int bz = z >> 2;
    const int b  = bz / NDO;
    const int oz = bz - b * NDO;
    if (ox >= NDO || oy >= NDO) return;

    const int plane = ND * NH * NW_ * 3;              // channel stride (floats)
    const float* xb = x + (long)b * NC * plane;       // batch base

    // Center point p for this output channel
    const int pOff = o * plane + (((oz + 1) * NH + (oy + 1)) * NW_ + (ox + 1)) * 3;
    const float px = __ldg(xb + pOff + 0);
    const float py = __ldg(xb + pOff + 1);
    const float pz = __ldg(xb + pOff + 2);

    float S[9];
#pragma unroll
    for (int j = 0; j < 9; j++) S[j] = 0.0f;

    const float CLIP_LO = (float)(-1.0 + 1e-6);
    const float CLIP_HI = (float)( 1.0 - 1e-6);

    const int wbase = o * NTAP * NC;
    const int vox0  = ((oz * NH + oy) * NW_ + ox) * 3;   // tap (0,0,0) corner

#pragma unroll 1
    for (int kz = 0; kz < 3; kz++) {
#pragma unroll 1
        for (int ky = 0; ky < 3; ky++) {
            const int rowOff = vox0 + ((kz * NH + ky) * NW_) * 3;
            const int tapRow = (kz * 3 + ky) * 3;
#pragma unroll
            for (int kx = 0; kx < 3; kx++) {
                const int tap  = tapRow + kx;
                const int qOff = rowOff + kx * 3;

#pragma unroll
                for (int i = 0; i < NC; i++) {
                    const float* q = xb + qOff + i * plane;
                    const float qx = __ldg(q + 0);
                    const float qy = __ldg(q + 1);
                    const float qz = __ldg(q + 2);

                    // dot SIMD-FOLD (LOCKED): (t0 + t2) + t1, rn, no fma
                    float d = __fadd_rn(__fadd_rn(__fmul_rn(px, qx),
                                                  __fmul_rn(pz, qz)),
                                        __fmul_rn(py, qy));
                    d = fminf(fmaxf(d, CLIP_LO), CLIP_HI);

                    // g = acos(d)/sin(acos(d)) — custom poly acos
                    const float s2 = fmaf(-d, d, 1.0f);   // exact near pole
                    const float g  = acos_fast(d) * rsqrtf(s2);

                    // lg = g * (q - d*p), contracted
                    const float lx = g * fmaf(-d, px, qx);
                    const float ly = g * fmaf(-d, py, qy);
                    const float lz = g * fmaf(-d, pz, qz);

                    const float4 wv = sw[wbase + tap * 4 + i];

                    S[0] = fmaf(wv.x, lx, S[0]);
                    S[1] = fmaf(wv.x, ly, S[1]);
                    S[2] = fmaf(wv.x, lz, S[2]);
                    S[3] = fmaf(wv.y, lx, S[3]);
                    S[4] = fmaf(wv.y, ly, S[4]);
                    S[5] = fmaf(wv.y, lz, S[5]);
                    S[6] = fmaf(wv.z, lx, S[6]);
                    S[7] = fmaf(wv.z, ly, S[7]);
                    S[8] = fmaf(wv.z, lz, S[8]);
                }
            }
        }
    }

    // v = log1 + log2*log3
    const float vx = fmaf(S[3], S[6], S[0]);
    const float vy = fmaf(S[4], S[7], S[1]);
    const float vz = fmaf(S[5], S[8], S[2]);

    // n = sqrt(|v|^2 + 1e-12)
    const float n2 = __fadd_rn(fmaf(vz, vz, fmaf(vy, vy, __fmul_rn(vx, vx))),
                               1e-12f);
    const float n  = sqrtf(n2);
    float sn, cn;
    sincosf(n, &sn, &cn);
    const float k = __fdiv_rn(sn, n);

    float* op = out + (((((long)b * NC + o) * NDO + oz) * NDO + oy) * NDO + ox) * 3;
    op[0] = fmaf(cn, px, __fmul_rn(k, vx));
    op[1] = fmaf(cn, py, __fmul_rn(k, vy));
    op[2] = fmaf(cn, pz, __fmul_rn(k, vz));
}

extern "C" void kernel_launch(void* const* d_in, const int* in_sizes, int n_in,
                              void* d_out, int out_size)
{
    const float* x  = (const float*)d_in[0];
    const float* w1 = (const float*)d_in[1];
    const float* w2 = (const float*)d_in[2];
    const float* w3 = (const float*)d_in[3];
    float* out = (float*)d_out;

    dim3 blk(32, 4, 1);
    dim3 grd((NDO + 31) / 32, (NDO + 3) / 4, 2 * NDO * NC);  // (2, 16, 496)
    mvv_kernel<<<grd, blk>>>(x, w1, w2, w3, out);
}